// round 16
// baseline (speedup 1.0000x reference)
#include <cuda_runtime.h>
#include <cuda_bf16.h>
#include <cstdint>

#define BATCH 16
#define CH    64
#define HW    4096   // 64*64 queries per batch
#define MKEY  1024   // 32*32 pooled keys per batch

// Scratch (static __device__ — no allocation allowed)
__device__ __nv_bfloat16 d_thetaB[BATCH * HW * 8];   // [B][N][8]  (pre-scaled by log2e)
__device__ __nv_bfloat16 d_phiB  [BATCH * MKEY * 8]; // [B][M][8]
__device__ __nv_bfloat16 d_gT    [BATCH * 32 * MKEY];// [B][32][M] channel-major

__device__ __forceinline__ float ex2f(float x) {
    float y; asm("ex2.approx.ftz.f32 %0, %1;" : "=f"(y) : "f"(x)); return y;
}
__device__ __forceinline__ uint32_t pack_bf16(float lo, float hi) {
    uint32_t r;
    asm("cvt.rn.satfinite.bf16x2.f32 %0, %1, %2;" : "=r"(r) : "f"(hi), "f"(lo));
    return r;
}
__device__ __forceinline__ void ffma2(unsigned long long& acc,
                                      unsigned long long a,
                                      unsigned long long b) {
    asm("fma.rn.f32x2 %0, %1, %2, %0;" : "+l"(acc) : "l"(a), "l"(b));
}
__device__ __forceinline__ unsigned long long bcast2(float v) {
    unsigned long long u;
    asm("mov.b64 %0, {%1, %1};" : "=l"(u) : "f"(v));
    return u;
}
__device__ __forceinline__ void unpack2(unsigned long long v, float& lo, float& hi) {
    asm("mov.b64 {%0, %1}, %2;" : "=f"(lo), "=f"(hi) : "l"(v));
}

// S-tile MMA: C(16x8) = A(16x8) x B(8x8), fresh accumulate
__device__ __forceinline__ void mma_s(float* c, uint32_t a0, uint32_t a1, uint32_t b) {
    asm("mma.sync.aligned.m16n8k8.row.col.f32.bf16.bf16.f32 "
        "{%0,%1,%2,%3}, {%4,%5}, {%6}, {%7,%7,%7,%7};"
        : "=f"(c[0]), "=f"(c[1]), "=f"(c[2]), "=f"(c[3])
        : "r"(a0), "r"(a1), "r"(b), "f"(0.f));
}
// PV MMA: D(16x8) += A(16x16) x B(16x8)
__device__ __forceinline__ void mma_pv(float* d, uint32_t p0, uint32_t p1,
                                       uint32_t p2, uint32_t p3,
                                       uint32_t b0, uint32_t b1) {
    asm("mma.sync.aligned.m16n8k16.row.col.f32.bf16.bf16.f32 "
        "{%0,%1,%2,%3}, {%4,%5,%6,%7}, {%8,%9}, {%0,%1,%2,%3};"
        : "+f"(d[0]), "+f"(d[1]), "+f"(d[2]), "+f"(d[3])
        : "r"(p0), "r"(p1), "r"(p2), "r"(p3), "r"(b0), "r"(b1));
}
// PV MMA, zero-init accumulate
__device__ __forceinline__ void mma_pv0(float* d, uint32_t p0, uint32_t p1,
                                        uint32_t p2, uint32_t p3,
                                        uint32_t b0, uint32_t b1) {
    asm("mma.sync.aligned.m16n8k16.row.col.f32.bf16.bf16.f32 "
        "{%0,%1,%2,%3}, {%4,%5,%6,%7}, {%8,%9}, {%10,%10,%10,%10};"
        : "=f"(d[0]), "=f"(d[1]), "=f"(d[2]), "=f"(d[3])
        : "r"(p0), "r"(p1), "r"(p2), "r"(p3), "r"(b0), "r"(b1), "f"(0.f));
}

// ===========================================================================
// Kernel 1: fused 1x1-conv projections (+ 2x2 maxpool), bf16 outputs
//   relayout: x as [c][px][r0r0 r1r1] (1 LDS.128), weights packed 8/slot
//   -> 3 LDS per channel-iter (was 8)
// ===========================================================================
__global__ void __launch_bounds__(256)
proj_kernel(const float* __restrict__ x,
            const float* __restrict__ w_th,   // [8][64]
            const float* __restrict__ w_ph,   // [8][64]
            const float* __restrict__ w_g)    // [32][64]
{
    __shared__ float sx2[64 * 128];   // [c][px][4]: (r0e0,r0e1,r1e0,r1e1)
    __shared__ float sW [8 * 64 * 8]; // [ty][c][8]: th, ph, g0, g8, g16, g24, pad2

    const int b  = blockIdx.y;
    const int r  = blockIdx.x;
    const int px = threadIdx.x;
    const int ty = threadIdx.y;
    const int tid = ty * 32 + px;

    {   // stage x rows 2r, 2r+1 into interleaved layout
        float2* s2 = (float2*)sx2;    // index: c*64 + px*2 + row
        const size_t xbase = (size_t)b * 64 * 4096 + (size_t)(2 * r) * 64;
        for (int i = tid; i < 2048; i += 256) {
            const int c = i >> 5, pos = i & 31;
            const float4 v =
                *(const float4*)(x + xbase + (size_t)c * 4096 + pos * 4);
            if (pos < 16) {           // row 2r, pixels 4pos..4pos+3
                s2[c * 64 + (2 * pos)     * 2] = make_float2(v.x, v.y);
                s2[c * 64 + (2 * pos + 1) * 2] = make_float2(v.z, v.w);
            } else {                  // row 2r+1
                const int q = pos - 16;
                s2[c * 64 + (2 * q)     * 2 + 1] = make_float2(v.x, v.y);
                s2[c * 64 + (2 * q + 1) * 2 + 1] = make_float2(v.z, v.w);
            }
        }
        // weights: 512 (ty,c) slots
        for (int i = tid; i < 512; i += 256) {
            const int tt = i >> 6, c = i & 63;
            float* d = sW + i * 8;
            d[0] = w_th[tt * 64 + c];
            d[1] = w_ph[tt * 64 + c];
            d[2] = w_g [tt * 64 + c];
            d[3] = w_g [(tt + 8)  * 64 + c];
            d[4] = w_g [(tt + 16) * 64 + c];
            d[5] = w_g [(tt + 24) * 64 + c];
            d[6] = 0.f; d[7] = 0.f;
        }
    }
    __syncthreads();

    unsigned long long th01 = 0ull, th23 = 0ull;
    unsigned long long p01[5], p23[5];
#pragma unroll
    for (int k = 0; k < 5; k++) { p01[k] = 0ull; p23[k] = 0ull; }

#pragma unroll 8
    for (int c = 0; c < 64; c++) {
        const ulonglong2 xv =
            *(const ulonglong2*)(sx2 + c * 128 + px * 4);   // LDS.128
        const unsigned long long a  = xv.x;   // row 2r pair
        const unsigned long long d2 = xv.y;   // row 2r+1 pair
        const float4 w0 = *(const float4*)(sW + (ty * 64 + c) * 8);      // bcast
        const float2 w1 = *(const float2*)(sW + (ty * 64 + c) * 8 + 4);  // bcast
        ffma2(th01, a, bcast2(w0.x));  ffma2(th23, d2, bcast2(w0.x));
        ffma2(p01[0], a, bcast2(w0.y)); ffma2(p23[0], d2, bcast2(w0.y));
        ffma2(p01[1], a, bcast2(w0.z)); ffma2(p23[1], d2, bcast2(w0.z));
        ffma2(p01[2], a, bcast2(w0.w)); ffma2(p23[2], d2, bcast2(w0.w));
        ffma2(p01[3], a, bcast2(w1.x)); ffma2(p23[3], d2, bcast2(w1.x));
        ffma2(p01[4], a, bcast2(w1.y)); ffma2(p23[4], d2, bcast2(w1.y));
    }

    {   // theta: [B][N][8] bf16, pre-scaled by log2(e)
        const float L2E = 1.44269504f;
        float th0, th1, th2, th3;
        unpack2(th01, th0, th1); unpack2(th23, th2, th3);
        const int n0 = 2 * r * 64 + 2 * px;
        __nv_bfloat16* thp = d_thetaB + (size_t)b * HW * 8;
        thp[(size_t)(n0)      * 8 + ty] = __float2bfloat16(th0 * L2E);
        thp[(size_t)(n0 + 1)  * 8 + ty] = __float2bfloat16(th1 * L2E);
        thp[(size_t)(n0 + 64) * 8 + ty] = __float2bfloat16(th2 * L2E);
        thp[(size_t)(n0 + 65) * 8 + ty] = __float2bfloat16(th3 * L2E);
    }
    {   // phi: [B][M][8] bf16 ; g: [B][32][M] bf16 (channel-major)
        const int m = r * 32 + px;
#pragma unroll
        for (int k = 0; k < 5; k++) {
            float v0, v1, v2, v3;
            unpack2(p01[k], v0, v1); unpack2(p23[k], v2, v3);
            const float v = fmaxf(fmaxf(v0, v1), fmaxf(v2, v3));
            const int ch = ty + 8 * k;
            if (ch < 8)
                d_phiB[((size_t)b * MKEY + m) * 8 + ch] = __float2bfloat16(v);
            else
                d_gT[((size_t)b * 32 + (ch - 8)) * MKEY + m] = __float2bfloat16(v);
        }
    }
}

// ===========================================================================
// Kernel 2: HMMA flash attention — pair-packed phi (1 LDS.128 / 2 iters),
//           frag-packed gT (2 LDS.128/iter), rowsum via ones-constant MMA,
//           fp32 ex2, HMMA w_o epilogue
//   grid = (16 q-tiles, B), 512 threads (16 warps x 16 queries), 2 CTAs/SM
//   SMEM (98560 B):
//     0:     sTh   256x8 bf16 natural                     (4096)
//     4096:  sPhi3 pair-packed: P*512 + lane*16           (16384)
//            16B = S-frags {E.k0, E.k8, O.k0, O.k8} for grps {2P, 2P+1}
//     20480: sGT2  frag-packed: grp*1152 + t*32 + (t>>2)*16  (73728)
//     94208: sWoB  16x68 uint32 packed w_o pairs          (4352)
// ===========================================================================
#define SM_TH   0
#define SM_PHI  4096
#define SM_GT   20480
#define SM_WOB  94208
#define GT_GRP_STRIDE 1152

__global__ void __launch_bounds__(512, 2)
attn_kernel(const float* __restrict__ x,
            const float* __restrict__ w_o,
            const float* __restrict__ gamma_p,
            float* __restrict__ out)
{
    extern __shared__ char smem[];
    const int tid = threadIdx.x, wid = tid >> 5, lane = tid & 31;
    const int b = blockIdx.y, qt = blockIdx.x;
    const int g  = lane >> 2;       // groupID 0..7
    const int qd = lane & 3;        // quad 0..3

    // ---- stage theta / phi3 (pair-packed) / gT2 (frag-packed) / w_o ----
    {
        if (tid < 256) {
            ((uint4*)(smem + SM_TH))[tid] =
                ((const uint4*)(d_thetaB + ((size_t)b * HW + qt * 256) * 8))[tid];

            // sPhi3: task (P, gr): P=tid>>3, gr=tid&7
            const int P = tid >> 3, gr = tid & 7;
            const uint4* ps = (const uint4*)(d_phiB + (size_t)b * MKEY * 8);
            const uint4 AE = ps[P * 32 + gr];
            const uint4 BE = ps[P * 32 + 8  + gr];
            const uint4 AO = ps[P * 32 + 16 + gr];
            const uint4 BO = ps[P * 32 + 24 + gr];
            uint4* dst = (uint4*)(smem + SM_PHI + P * 512);
            dst[gr * 4 + 0] = make_uint4(AE.x, BE.x, AO.x, BO.x);
            dst[gr * 4 + 1] = make_uint4(AE.y, BE.y, AO.y, BO.y);
            dst[gr * 4 + 2] = make_uint4(AE.z, BE.z, AO.z, BO.z);
            dst[gr * 4 + 3] = make_uint4(AE.w, BE.w, AO.w, BO.w);
        }

        // sGT2: task (ch, grp), frag-contiguous 32B per (lane) per group
        {
            const uint32_t* gsrc = (const uint32_t*)(d_gT + (size_t)b * 32 * MKEY);
            for (int it = tid; it < 2048; it += 512) {
                const int ch = it >> 6, grp = it & 63;
                const int gg = ch & 7, jj = ch >> 3;
                const uint4 lo4 = ((const uint4*)gsrc)[ch * 128 + grp * 2];      // w=0..3
                const uint4 hi4 = ((const uint4*)gsrc)[ch * 128 + grp * 2 + 1];  // w=4..7
                char* base = smem + SM_GT + grp * GT_GRP_STRIDE;
                const uint32_t lv[4] = {lo4.x, lo4.y, lo4.z, lo4.w};
                const uint32_t hv[4] = {hi4.x, hi4.y, hi4.z, hi4.w};
#pragma unroll
                for (int q = 0; q < 4; q++) {
                    const int t = gg * 4 + q;
                    *(uint2*)(base + t * 32 + (t >> 2) * 16 + jj * 8) =
                        make_uint2(lv[q], hv[q]);
                }
            }
        }

        // w_o pairs: sWoB[p][n] = pack(w_o[n][2p], w_o[n][2p+1]), stride 68
        for (int i = tid; i < 1024; i += 512) {
            const int p = i >> 6, n = i & 63;
            const float2 f2 = *(const float2*)(w_o + n * 32 + 2 * p);
            ((uint32_t*)(smem + SM_WOB))[p * 68 + n] = pack_bf16(f2.x, f2.y);
        }
    }
    __syncthreads();

    // ---- per-warp theta A fragment (16 queries) ----
    const int qrow = wid * 16;
    const uint32_t a0 = *(const uint32_t*)(smem + SM_TH + ((qrow + g)     * 8 + 2 * qd) * 2);
    const uint32_t a1 = *(const uint32_t*)(smem + SM_TH + ((qrow + 8 + g) * 8 + 2 * qd) * 2);

    const uint32_t ones_b = (g == 0) ? 0x3F803F80u : 0u;   // rowsum column const

    float O[20];                     // j=0..3: PV cols 0..31 ; j=4: rowsum col 32
#pragma unroll
    for (int i = 0; i < 20; i++) O[i] = 0.f;

    const uint32_t phi_off = (uint32_t)(SM_PHI + lane * 16);
    const uint32_t gt_off  = (uint32_t)(SM_GT + lane * 32 + (lane >> 2) * 16);

#pragma unroll 2
    for (int P = 0; P < 32; P++) {
        const uint4 bp2 = *(const uint4*)(smem + phi_off + P * 512);

#pragma unroll
        for (int h = 0; h < 2; h++) {          // even / odd group of the pair
            const uint32_t bx = h ? bp2.z : bp2.x;
            const uint32_t by = h ? bp2.w : bp2.y;

            float c0[4], c1[4];
            mma_s(c0, a0, a1, bx);
            mma_s(c1, a0, a1, by);
            const uint32_t pa0 = pack_bf16(ex2f(c0[0]), ex2f(c0[1]));
            const uint32_t pa1 = pack_bf16(ex2f(c0[2]), ex2f(c0[3]));
            const uint32_t pa2 = pack_bf16(ex2f(c1[0]), ex2f(c1[1]));
            const uint32_t pa3 = pack_bf16(ex2f(c1[2]), ex2f(c1[3]));

            const char* gp = smem + gt_off + (2 * P + h) * GT_GRP_STRIDE;
            const uint4 gv0 = *(const uint4*)(gp);        // j=0,1 B-frags
            const uint4 gv1 = *(const uint4*)(gp + 16);   // j=2,3 B-frags

            mma_pv(O + 0,  pa0, pa1, pa2, pa3, gv0.x, gv0.y);
            mma_pv(O + 4,  pa0, pa1, pa2, pa3, gv0.z, gv0.w);
            mma_pv(O + 8,  pa0, pa1, pa2, pa3, gv1.x, gv1.y);
            mma_pv(O + 12, pa0, pa1, pa2, pa3, gv1.z, gv1.w);
            mma_pv(O + 16, pa0, pa1, pa2, pa3, ones_b, ones_b);   // rowsum
        }
    }

    // ---- per-row scales from the rowsum column (col 32, held by qd==0) ----
    const float sum0 = __shfl_sync(0xffffffff, O[16], lane & 28);
    const float sum1 = __shfl_sync(0xffffffff, O[18], lane & 28);
    const float gma  = gamma_p[0];
    const float scale0 = gma / sum0;
    const float scale1 = gma / sum1;

    // ---- O -> bf16 A-frags for the w_o HMMA epilogue ----
    const uint32_t oa0 = pack_bf16(O[0],  O[1]);   // k-tile 0 (ch 0..15)
    const uint32_t oa1 = pack_bf16(O[2],  O[3]);
    const uint32_t oa2 = pack_bf16(O[4],  O[5]);
    const uint32_t oa3 = pack_bf16(O[6],  O[7]);
    const uint32_t ob0 = pack_bf16(O[8],  O[9]);   // k-tile 1 (ch 16..31)
    const uint32_t ob1 = pack_bf16(O[10], O[11]);
    const uint32_t ob2 = pack_bf16(O[12], O[13]);
    const uint32_t ob3 = pack_bf16(O[14], O[15]);

    const uint32_t* wob = (const uint32_t*)(smem + SM_WOB);
    const int q0 = qt * 256 + qrow + g;
    const float* xb = x   + (size_t)b * CH * HW;
    float*       obp = out + (size_t)b * CH * HW;

#pragma unroll
    for (int t = 0; t < 8; t++) {                  // 8 n-tiles of 8 output chans
        const int n = t * 8 + g;
        float F[4];
        mma_pv0(F, oa0, oa1, oa2, oa3, wob[qd * 68 + n],       wob[(qd + 4) * 68 + n]);
        mma_pv (F, ob0, ob1, ob2, ob3, wob[(8 + qd) * 68 + n], wob[(12 + qd) * 68 + n]);
        const int oc = t * 8 + 2 * qd;
        obp[(size_t)oc * HW + q0]           = scale0 * F[0] + xb[(size_t)oc * HW + q0];
        obp[(size_t)(oc + 1) * HW + q0]     = scale0 * F[1] + xb[(size_t)(oc + 1) * HW + q0];
        obp[(size_t)oc * HW + q0 + 8]       = scale1 * F[2] + xb[(size_t)oc * HW + q0 + 8];
        obp[(size_t)(oc + 1) * HW + q0 + 8] = scale1 * F[3] + xb[(size_t)(oc + 1) * HW + q0 + 8];
    }
}

// ===========================================================================
extern "C" void kernel_launch(void* const* d_in, const int* in_sizes, int n_in,
                              void* d_out, int out_size) {
    const float* x     = (const float*)d_in[0];
    const float* w_th  = (const float*)d_in[1];
    const float* w_ph  = (const float*)d_in[2];
    const float* w_g   = (const float*)d_in[3];
    const float* w_o   = (const float*)d_in[4];
    const float* gamma = (const float*)d_in[5];
    float* out = (float*)d_out;

    proj_kernel<<<dim3(32, BATCH), dim3(32, 8)>>>(x, w_th, w_ph, w_g);

    const int smem_bytes = 98560;
    cudaFuncSetAttribute(attn_kernel,
                         cudaFuncAttributeMaxDynamicSharedMemorySize, smem_bytes);
    attn_kernel<<<dim3(16, BATCH), 512, smem_bytes>>>(x, w_o, gamma, out);
}

// round 17
// speedup vs baseline: 1.0860x; 1.0860x over previous
#include <cuda_runtime.h>
#include <cuda_bf16.h>
#include <cstdint>

#define BATCH 16
#define CH    64
#define HW    4096   // 64*64 queries per batch
#define MKEY  1024   // 32*32 pooled keys per batch

// Scratch (static __device__ — no allocation allowed)
__device__ __nv_bfloat16 d_thetaB[BATCH * HW * 8];   // [B][N][8]  (pre-scaled by log2e)
__device__ __nv_bfloat16 d_phiB  [BATCH * MKEY * 8]; // [B][M][8]
__device__ __nv_bfloat16 d_gT    [BATCH * 32 * MKEY];// [B][32][M] channel-major

__device__ __forceinline__ float ex2f(float x) {
    float y; asm("ex2.approx.ftz.f32 %0, %1;" : "=f"(y) : "f"(x)); return y;
}
__device__ __forceinline__ uint32_t pack_bf16(float lo, float hi) {
    uint32_t r;
    asm("cvt.rn.satfinite.bf16x2.f32 %0, %1, %2;" : "=r"(r) : "f"(hi), "f"(lo));
    return r;
}
__device__ __forceinline__ void ffma2(unsigned long long& acc,
                                      unsigned long long a,
                                      unsigned long long b) {
    asm("fma.rn.f32x2 %0, %1, %2, %0;" : "+l"(acc) : "l"(a), "l"(b));
}
__device__ __forceinline__ unsigned long long bcast2(float v) {
    unsigned long long u;
    asm("mov.b64 %0, {%1, %1};" : "=l"(u) : "f"(v));
    return u;
}
__device__ __forceinline__ void unpack2(unsigned long long v, float& lo, float& hi) {
    asm("mov.b64 {%0, %1}, %2;" : "=f"(lo), "=f"(hi) : "l"(v));
}

// S-tile MMA: C(16x8) = A(16x8) x B(8x8), fresh accumulate
__device__ __forceinline__ void mma_s(float* c, uint32_t a0, uint32_t a1, uint32_t b) {
    asm("mma.sync.aligned.m16n8k8.row.col.f32.bf16.bf16.f32 "
        "{%0,%1,%2,%3}, {%4,%5}, {%6}, {%7,%7,%7,%7};"
        : "=f"(c[0]), "=f"(c[1]), "=f"(c[2]), "=f"(c[3])
        : "r"(a0), "r"(a1), "r"(b), "f"(0.f));
}
// PV MMA: D(16x8) += A(16x16) x B(16x8)
__device__ __forceinline__ void mma_pv(float* d, uint32_t p0, uint32_t p1,
                                       uint32_t p2, uint32_t p3,
                                       uint32_t b0, uint32_t b1) {
    asm("mma.sync.aligned.m16n8k16.row.col.f32.bf16.bf16.f32 "
        "{%0,%1,%2,%3}, {%4,%5,%6,%7}, {%8,%9}, {%0,%1,%2,%3};"
        : "+f"(d[0]), "+f"(d[1]), "+f"(d[2]), "+f"(d[3])
        : "r"(p0), "r"(p1), "r"(p2), "r"(p3), "r"(b0), "r"(b1));
}
// PV MMA, zero-init accumulate
__device__ __forceinline__ void mma_pv0(float* d, uint32_t p0, uint32_t p1,
                                        uint32_t p2, uint32_t p3,
                                        uint32_t b0, uint32_t b1) {
    asm("mma.sync.aligned.m16n8k16.row.col.f32.bf16.bf16.f32 "
        "{%0,%1,%2,%3}, {%4,%5,%6,%7}, {%8,%9}, {%10,%10,%10,%10};"
        : "=f"(d[0]), "=f"(d[1]), "=f"(d[2]), "=f"(d[3])
        : "r"(p0), "r"(p1), "r"(p2), "r"(p3), "r"(b0), "r"(b1), "f"(0.f));
}

// ===========================================================================
// Kernel 1: fused 1x1-conv projections (+ 2x2 maxpool), bf16 outputs
//   relayout: x as [c][px][r0r0 r1r1] (1 LDS.128), weights packed 8/slot
//   -> 3 LDS per channel-iter (was 8)    [proven win in R15/16]
// ===========================================================================
__global__ void __launch_bounds__(256)
proj_kernel(const float* __restrict__ x,
            const float* __restrict__ w_th,   // [8][64]
            const float* __restrict__ w_ph,   // [8][64]
            const float* __restrict__ w_g)    // [32][64]
{
    __shared__ float sx2[64 * 128];   // [c][px][4]: (r0e0,r0e1,r1e0,r1e1)
    __shared__ float sW [8 * 64 * 8]; // [ty][c][8]: th, ph, g0, g8, g16, g24, pad2

    const int b  = blockIdx.y;
    const int r  = blockIdx.x;
    const int px = threadIdx.x;
    const int ty = threadIdx.y;
    const int tid = ty * 32 + px;

    {   // stage x rows 2r, 2r+1 into interleaved layout
        float2* s2 = (float2*)sx2;    // index: c*64 + px*2 + row
        const size_t xbase = (size_t)b * 64 * 4096 + (size_t)(2 * r) * 64;
        for (int i = tid; i < 2048; i += 256) {
            const int c = i >> 5, pos = i & 31;
            const float4 v =
                *(const float4*)(x + xbase + (size_t)c * 4096 + pos * 4);
            if (pos < 16) {           // row 2r, pixels 4pos..4pos+3
                s2[c * 64 + (2 * pos)     * 2] = make_float2(v.x, v.y);
                s2[c * 64 + (2 * pos + 1) * 2] = make_float2(v.z, v.w);
            } else {                  // row 2r+1
                const int q = pos - 16;
                s2[c * 64 + (2 * q)     * 2 + 1] = make_float2(v.x, v.y);
                s2[c * 64 + (2 * q + 1) * 2 + 1] = make_float2(v.z, v.w);
            }
        }
        // weights: 512 (ty,c) slots
        for (int i = tid; i < 512; i += 256) {
            const int tt = i >> 6, c = i & 63;
            float* d = sW + i * 8;
            d[0] = w_th[tt * 64 + c];
            d[1] = w_ph[tt * 64 + c];
            d[2] = w_g [tt * 64 + c];
            d[3] = w_g [(tt + 8)  * 64 + c];
            d[4] = w_g [(tt + 16) * 64 + c];
            d[5] = w_g [(tt + 24) * 64 + c];
            d[6] = 0.f; d[7] = 0.f;
        }
    }
    __syncthreads();

    unsigned long long th01 = 0ull, th23 = 0ull;
    unsigned long long p01[5], p23[5];
#pragma unroll
    for (int k = 0; k < 5; k++) { p01[k] = 0ull; p23[k] = 0ull; }

#pragma unroll 8
    for (int c = 0; c < 64; c++) {
        const ulonglong2 xv =
            *(const ulonglong2*)(sx2 + c * 128 + px * 4);   // LDS.128
        const unsigned long long a  = xv.x;   // row 2r pair
        const unsigned long long d2 = xv.y;   // row 2r+1 pair
        const float4 w0 = *(const float4*)(sW + (ty * 64 + c) * 8);      // bcast
        const float2 w1 = *(const float2*)(sW + (ty * 64 + c) * 8 + 4);  // bcast
        ffma2(th01, a, bcast2(w0.x));  ffma2(th23, d2, bcast2(w0.x));
        ffma2(p01[0], a, bcast2(w0.y)); ffma2(p23[0], d2, bcast2(w0.y));
        ffma2(p01[1], a, bcast2(w0.z)); ffma2(p23[1], d2, bcast2(w0.z));
        ffma2(p01[2], a, bcast2(w0.w)); ffma2(p23[2], d2, bcast2(w0.w));
        ffma2(p01[3], a, bcast2(w1.x)); ffma2(p23[3], d2, bcast2(w1.x));
        ffma2(p01[4], a, bcast2(w1.y)); ffma2(p23[4], d2, bcast2(w1.y));
    }

    {   // theta: [B][N][8] bf16, pre-scaled by log2(e)
        const float L2E = 1.44269504f;
        float th0, th1, th2, th3;
        unpack2(th01, th0, th1); unpack2(th23, th2, th3);
        const int n0 = 2 * r * 64 + 2 * px;
        __nv_bfloat16* thp = d_thetaB + (size_t)b * HW * 8;
        thp[(size_t)(n0)      * 8 + ty] = __float2bfloat16(th0 * L2E);
        thp[(size_t)(n0 + 1)  * 8 + ty] = __float2bfloat16(th1 * L2E);
        thp[(size_t)(n0 + 64) * 8 + ty] = __float2bfloat16(th2 * L2E);
        thp[(size_t)(n0 + 65) * 8 + ty] = __float2bfloat16(th3 * L2E);
    }
    {   // phi: [B][M][8] bf16 ; g: [B][32][M] bf16 (channel-major)
        const int m = r * 32 + px;
#pragma unroll
        for (int k = 0; k < 5; k++) {
            float v0, v1, v2, v3;
            unpack2(p01[k], v0, v1); unpack2(p23[k], v2, v3);
            const float v = fmaxf(fmaxf(v0, v1), fmaxf(v2, v3));
            const int ch = ty + 8 * k;
            if (ch < 8)
                d_phiB[((size_t)b * MKEY + m) * 8 + ch] = __float2bfloat16(v);
            else
                d_gT[((size_t)b * 32 + (ch - 8)) * MKEY + m] = __float2bfloat16(v);
        }
    }
}

// ===========================================================================
// Kernel 2: HMMA flash attention — R14's proven-best loop:
//   frag-packed phi (1 LDS.64/iter), permuted gT stride-2080 (4 LDS.64/iter),
//   rowsum via ones-constant MMA, fp32 ex2, HMMA w_o epilogue
//   grid = (16 q-tiles, B), 512 threads (16 warps x 16 queries), 2 CTAs/SM
//   SMEM (91392 B):
//     0:     sTh   256x8 bf16 natural                    (4096)
//     4096:  sPhi2 frag-packed: grp*256 + lane*8         (16384)
//     20480: sGT   32 rows x 2080 B, key-pair-permuted   (66560)
//     87040: sWoB  16x68 uint32 packed w_o pairs         (4352)
// ===========================================================================
#define SM_TH   0
#define SM_PHI  4096
#define SM_GT   20480
#define SM_WOB  87040
#define GT_STRIDE 2080   // bytes; == 32 mod 256 -> conflict-free LDS.64

__global__ void __launch_bounds__(512, 2)
attn_kernel(const float* __restrict__ x,
            const float* __restrict__ w_o,
            const float* __restrict__ gamma_p,
            float* __restrict__ out)
{
    extern __shared__ char smem[];
    const int tid = threadIdx.x, wid = tid >> 5, lane = tid & 31;
    const int b = blockIdx.y, qt = blockIdx.x;
    const int g  = lane >> 2;       // groupID 0..7
    const int qd = lane & 3;        // quad 0..3

    // ---- stage theta / phi2 (frag-packed) / gT (permuted) / w_o pairs ----
    {
        if (tid < 256)
            ((uint4*)(smem + SM_TH))[tid] =
                ((const uint4*)(d_thetaB + ((size_t)b * HW + qt * 256) * 8))[tid];

        // sPhi2: task (grp, gr): pack both S-tile B-frags per (gr, qd') into 8B
        {
            const int grp = tid >> 3, gr = tid & 7;   // 64 x 8 = 512 tasks
            const uint4 A  = ((const uint4*)(d_phiB + (size_t)b * MKEY * 8))[grp * 16 + gr];
            const uint4 Bv = ((const uint4*)(d_phiB + (size_t)b * MKEY * 8))[grp * 16 + 8 + gr];
            uint2* dst = (uint2*)(smem + SM_PHI + grp * 256 + gr * 32);
            dst[0] = make_uint2(A.x, Bv.x);
            dst[1] = make_uint2(A.y, Bv.y);
            dst[2] = make_uint2(A.z, Bv.z);
            dst[3] = make_uint2(A.w, Bv.w);
        }

        // gT: permute pairs within each 16-key group: pos_pair = (w&3)*2 + (w>>2)
        const uint4* gsrc = (const uint4*)(d_gT + (size_t)b * 32 * MKEY);
        for (int i = tid; i < 4096; i += 512) {
            const int ch = i >> 7, u4 = i & 127;       // u4 -> pairs 4u4..4u4+3
            const uint4 v = gsrc[ch * 128 + u4];
            char* rowp = smem + SM_GT + ch * GT_STRIDE;
            const uint32_t vv[4] = {v.x, v.y, v.z, v.w};
#pragma unroll
            for (int s = 0; s < 4; s++) {
                const int p = u4 * 4 + s;              // global pair index
                const int grp = p >> 3, w = p & 7;
                const int pos = (w & 3) * 2 + (w >> 2);
                *(uint32_t*)(rowp + (grp * 8 + pos) * 4) = vv[s];
            }
        }

        // w_o pairs: sWoB[p][n] = pack(w_o[n][2p], w_o[n][2p+1]), stride 68
        for (int i = tid; i < 1024; i += 512) {
            const int p = i >> 6, n = i & 63;
            const float2 f2 = *(const float2*)(w_o + n * 32 + 2 * p);
            ((uint32_t*)(smem + SM_WOB))[p * 68 + n] = pack_bf16(f2.x, f2.y);
        }
    }
    __syncthreads();

    // ---- per-warp theta A fragment (16 queries) ----
    const int qrow = wid * 16;
    const uint32_t a0 = *(const uint32_t*)(smem + SM_TH + ((qrow + g)     * 8 + 2 * qd) * 2);
    const uint32_t a1 = *(const uint32_t*)(smem + SM_TH + ((qrow + 8 + g) * 8 + 2 * qd) * 2);

    const uint32_t ones_b = (g == 0) ? 0x3F803F80u : 0u;   // rowsum column const

    float O[20];                     // j=0..3: PV cols 0..31 ; j=4: rowsum col 32
#pragma unroll
    for (int i = 0; i < 20; i++) O[i] = 0.f;

    const uint32_t phi_off = (uint32_t)(SM_PHI + lane * 8);

#pragma unroll 2
    for (int grp = 0; grp < 64; grp++) {
        const uint2 bp = *(const uint2*)(smem + phi_off + grp * 256);

        float c[8];
        mma_s(c + 0, a0, a1, bp.x);
        mma_s(c + 4, a0, a1, bp.y);

#pragma unroll
        for (int i = 0; i < 8; i++) c[i] = ex2f(c[i]);
        const uint32_t pa0 = pack_bf16(c[0], c[1]);
        const uint32_t pa1 = pack_bf16(c[2], c[3]);
        const uint32_t pa2 = pack_bf16(c[4], c[5]);
        const uint32_t pa3 = pack_bf16(c[6], c[7]);

        // O += P(16x16) * g(16x32): permuted layout -> one LDS.64 per j
        const char* gb = smem + SM_GT + grp * 32 + 8 * qd;
#pragma unroll
        for (int j = 0; j < 4; j++) {
            uint32_t b0, b1;
            asm("ld.shared.v2.b32 {%0,%1}, [%2];"
                : "=r"(b0), "=r"(b1)
                : "r"((uint32_t)__cvta_generic_to_shared(gb + (j * 8 + g) * GT_STRIDE)));
            mma_pv(O + 4 * j, pa0, pa1, pa2, pa3, b0, b1);
        }
        mma_pv(O + 16, pa0, pa1, pa2, pa3, ones_b, ones_b);   // rowsum
    }

    // ---- per-row scales from the rowsum column (col 32, held by qd==0) ----
    const float sum0 = __shfl_sync(0xffffffff, O[16], lane & 28);
    const float sum1 = __shfl_sync(0xffffffff, O[18], lane & 28);
    const float gma  = gamma_p[0];
    const float scale0 = gma / sum0;
    const float scale1 = gma / sum1;

    // ---- O -> bf16 A-frags for the w_o HMMA epilogue ----
    const uint32_t oa0 = pack_bf16(O[0],  O[1]);   // k-tile 0 (ch 0..15)
    const uint32_t oa1 = pack_bf16(O[2],  O[3]);
    const uint32_t oa2 = pack_bf16(O[4],  O[5]);
    const uint32_t oa3 = pack_bf16(O[6],  O[7]);
    const uint32_t ob0 = pack_bf16(O[8],  O[9]);   // k-tile 1 (ch 16..31)
    const uint32_t ob1 = pack_bf16(O[10], O[11]);
    const uint32_t ob2 = pack_bf16(O[12], O[13]);
    const uint32_t ob3 = pack_bf16(O[14], O[15]);

    const uint32_t* wob = (const uint32_t*)(smem + SM_WOB);
    const int q0 = qt * 256 + qrow + g;
    const float* xb = x   + (size_t)b * CH * HW;
    float*       obp = out + (size_t)b * CH * HW;

#pragma unroll
    for (int t = 0; t < 8; t++) {                  // 8 n-tiles of 8 output chans
        const int n = t * 8 + g;
        float F[4];
        mma_pv0(F, oa0, oa1, oa2, oa3, wob[qd * 68 + n],       wob[(qd + 4) * 68 + n]);
        mma_pv (F, ob0, ob1, ob2, ob3, wob[(8 + qd) * 68 + n], wob[(12 + qd) * 68 + n]);
        const int oc = t * 8 + 2 * qd;
        obp[(size_t)oc * HW + q0]           = scale0 * F[0] + xb[(size_t)oc * HW + q0];
        obp[(size_t)(oc + 1) * HW + q0]     = scale0 * F[1] + xb[(size_t)(oc + 1) * HW + q0];
        obp[(size_t)oc * HW + q0 + 8]       = scale1 * F[2] + xb[(size_t)oc * HW + q0 + 8];
        obp[(size_t)(oc + 1) * HW + q0 + 8] = scale1 * F[3] + xb[(size_t)(oc + 1) * HW + q0 + 8];
    }
}

// ===========================================================================
extern "C" void kernel_launch(void* const* d_in, const int* in_sizes, int n_in,
                              void* d_out, int out_size) {
    const float* x     = (const float*)d_in[0];
    const float* w_th  = (const float*)d_in[1];
    const float* w_ph  = (const float*)d_in[2];
    const float* w_g   = (const float*)d_in[3];
    const float* w_o   = (const float*)d_in[4];
    const float* gamma = (const float*)d_in[5];
    float* out = (float*)d_out;

    proj_kernel<<<dim3(32, BATCH), dim3(32, 8)>>>(x, w_th, w_ph, w_g);

    const int smem_bytes = 91392;
    cudaFuncSetAttribute(attn_kernel,
                         cudaFuncAttributeMaxDynamicSharedMemorySize, smem_bytes);
    attn_kernel<<<dim3(16, BATCH), 512, smem_bytes>>>(x, w_o, gamma, out);
}